// round 1
// baseline (speedup 1.0000x reference)
#include <cuda_runtime.h>
#include <math.h>

#define N_NODES   4000
#define N_LAYERS  8
#define PER_LAYER 500
#define IN_DEG    32
#define BATCH     2048
#define IN_DIM    784
#define OUT_DIM   10
#define EDGES_PER_LAYER (PER_LAYER * IN_DEG)   /* 16000 */
#define NCHUNKS   8

/* Scratch (device globals: allocation-free per harness rules) */
__device__ float g_h[(size_t)N_NODES * BATCH];              /* 32 MB activations, vertex-major */
__device__ float g_part[NCHUNKS * BATCH * OUT_DIM];         /* output partial sums */

/* ------------------------------------------------------------------ */
/* Kernel 1: h[0:500] = relu(W_in @ x^T + b_in)   [PER_LAYER, BATCH]  */
/* Tiled fp32 GEMM: BM=64, BN=64, BK=16, 256 threads, 4x4 microtile   */
/* ------------------------------------------------------------------ */
#define BM 64
#define BN 64
#define BK 16

__global__ __launch_bounds__(256) void gemm_in_kernel(
    const float* __restrict__ x,      /* [BATCH, IN_DIM] */
    const float* __restrict__ W,      /* [PER_LAYER, IN_DIM] */
    const float* __restrict__ bias)   /* [PER_LAYER] */
{
    __shared__ float As[BK][BM + 4];  /* As[k][m] = W[m][k] */
    __shared__ float Bs[BK][BN + 4];  /* Bs[k][n] = x[n][k] */

    const int tid = threadIdx.x;
    const int m0 = blockIdx.y * BM;
    const int n0 = blockIdx.x * BN;

    const int tx = tid % 16;          /* n micro-tile */
    const int ty = tid / 16;          /* m micro-tile */

    /* cooperative load mapping: 256 threads load 64 rows x 16 k (4 k each) */
    const int lr = tid / 4;           /* 0..63 row within tile */
    const int lk = (tid % 4) * 4;     /* 0,4,8,12 */

    float acc[4][4] = {};

    for (int k0 = 0; k0 < IN_DIM; k0 += BK) {
        /* load A tile (W_in), guard rows >= PER_LAYER */
        float4 av = make_float4(0.f, 0.f, 0.f, 0.f);
        const int gm = m0 + lr;
        const int gk = k0 + lk;                    /* IN_DIM % 16 == 0, in-bounds */
        if (gm < PER_LAYER)
            av = *reinterpret_cast<const float4*>(&W[(size_t)gm * IN_DIM + gk]);
        As[lk + 0][lr] = av.x;
        As[lk + 1][lr] = av.y;
        As[lk + 2][lr] = av.z;
        As[lk + 3][lr] = av.w;

        /* load B tile (x): n dimension always in bounds (2048 % 64 == 0) */
        const float4 bv = *reinterpret_cast<const float4*>(&x[(size_t)(n0 + lr) * IN_DIM + gk]);
        Bs[lk + 0][lr] = bv.x;
        Bs[lk + 1][lr] = bv.y;
        Bs[lk + 2][lr] = bv.z;
        Bs[lk + 3][lr] = bv.w;

        __syncthreads();

        #pragma unroll
        for (int k = 0; k < BK; k++) {
            const float4 a = *reinterpret_cast<const float4*>(&As[k][ty * 4]);
            const float4 b = *reinterpret_cast<const float4*>(&Bs[k][tx * 4]);
            acc[0][0] += a.x * b.x; acc[0][1] += a.x * b.y; acc[0][2] += a.x * b.z; acc[0][3] += a.x * b.w;
            acc[1][0] += a.y * b.x; acc[1][1] += a.y * b.y; acc[1][2] += a.y * b.z; acc[1][3] += a.y * b.w;
            acc[2][0] += a.z * b.x; acc[2][1] += a.z * b.y; acc[2][2] += a.z * b.z; acc[2][3] += a.z * b.w;
            acc[3][0] += a.w * b.x; acc[3][1] += a.w * b.y; acc[3][2] += a.w * b.z; acc[3][3] += a.w * b.w;
        }
        __syncthreads();
    }

    #pragma unroll
    for (int i = 0; i < 4; i++) {
        const int m = m0 + ty * 4 + i;
        if (m < PER_LAYER) {
            const float bb = bias[m];
            float4 r;
            r.x = fmaxf(acc[i][0] + bb, 0.f);
            r.y = fmaxf(acc[i][1] + bb, 0.f);
            r.z = fmaxf(acc[i][2] + bb, 0.f);
            r.w = fmaxf(acc[i][3] + bb, 0.f);
            *reinterpret_cast<float4*>(&g_h[(size_t)m * BATCH + n0 + tx * 4]) = r;
        }
    }
}

/* ------------------------------------------------------------------ */
/* Kernel 2: one DAG layer.  For vertex v: relu(sum_e w[e]*h[src[e]])  */
/* Grid: (BATCH/(128*4), PER_LAYER); block 128 threads, float4/thread  */
/* ------------------------------------------------------------------ */
__global__ __launch_bounds__(128) void spmm_layer_kernel(
    const float* __restrict__ w_edge,
    const int*   __restrict__ edge_src,
    const int layer)
{
    const int v = blockIdx.y;
    const int c = (blockIdx.x * blockDim.x + threadIdx.x) * 4;
    const int base = (layer - 1) * EDGES_PER_LAYER + v * IN_DEG;

    __shared__ int   s_src[IN_DEG];
    __shared__ float s_w[IN_DEG];
    if (threadIdx.x < IN_DEG) {
        s_src[threadIdx.x] = edge_src[base + threadIdx.x];
        s_w[threadIdx.x]   = w_edge[base + threadIdx.x];
    }
    __syncthreads();

    float4 acc = make_float4(0.f, 0.f, 0.f, 0.f);
    #pragma unroll 8
    for (int e = 0; e < IN_DEG; e++) {
        const float w  = s_w[e];
        const float4 hv = *reinterpret_cast<const float4*>(
            &g_h[(size_t)s_src[e] * BATCH + c]);
        acc.x += w * hv.x;
        acc.y += w * hv.y;
        acc.z += w * hv.z;
        acc.w += w * hv.w;
    }

    const int dst = layer * PER_LAYER + v;
    float4 r;
    r.x = fmaxf(acc.x, 0.f);
    r.y = fmaxf(acc.y, 0.f);
    r.z = fmaxf(acc.z, 0.f);
    r.w = fmaxf(acc.w, 0.f);
    *reinterpret_cast<float4*>(&g_h[(size_t)dst * BATCH + c]) = r;
}

/* ------------------------------------------------------------------ */
/* Kernel 3a: partial output GEMV over v-chunks (deterministic)        */
/* grid (BATCH/256, NCHUNKS), 256 threads; thread = one batch element  */
/* ------------------------------------------------------------------ */
__global__ __launch_bounds__(256) void out_partial_kernel(
    const float* __restrict__ W_out,     /* [OUT_DIM, v_out] */
    const int*   __restrict__ out_verts, /* [v_out] */
    const int v_out)
{
    const int b = blockIdx.x * blockDim.x + threadIdx.x;
    const int chunk = blockIdx.y;
    const int csz = (v_out + NCHUNKS - 1) / NCHUNKS;
    const int v0 = chunk * csz;
    const int v1 = (v0 + csz < v_out) ? (v0 + csz) : v_out;

    float acc[OUT_DIM];
    #pragma unroll
    for (int o = 0; o < OUT_DIM; o++) acc[o] = 0.f;

    for (int v = v0; v < v1; v++) {
        const int vert = __ldg(&out_verts[v]);                 /* uniform */
        const float hv = g_h[(size_t)vert * BATCH + b];        /* coalesced */
        #pragma unroll
        for (int o = 0; o < OUT_DIM; o++)
            acc[o] += hv * __ldg(&W_out[(size_t)o * v_out + v]); /* uniform, L1 */
    }

    float* p = &g_part[((size_t)chunk * BATCH + b) * OUT_DIM];
    #pragma unroll
    for (int o = 0; o < OUT_DIM; o++) p[o] = acc[o];
}

/* Kernel 3b: reduce partials + bias -> d_out [BATCH, OUT_DIM] */
__global__ __launch_bounds__(256) void out_final_kernel(
    const float* __restrict__ b_out,
    float* __restrict__ out)
{
    const int idx = blockIdx.x * blockDim.x + threadIdx.x;
    if (idx < BATCH * OUT_DIM) {
        const int o = idx % OUT_DIM;
        float s = b_out[o];
        #pragma unroll
        for (int c = 0; c < NCHUNKS; c++)
            s += g_part[(size_t)c * BATCH * OUT_DIM + idx];
        out[idx] = s;
    }
}

/* ------------------------------------------------------------------ */
extern "C" void kernel_launch(void* const* d_in, const int* in_sizes, int n_in,
                              void* d_out, int out_size)
{
    /* metadata order: x, W_in, b_in, w_edge, W_out, b_out,
       edge_src, edge_dst_local, [edge_offsets], out_verts.
       edge_offsets may or may not be surfaced -> index out_verts from the end. */
    const float* x        = (const float*)d_in[0];
    const float* W_in     = (const float*)d_in[1];
    const float* b_in     = (const float*)d_in[2];
    const float* w_edge   = (const float*)d_in[3];
    const float* W_out    = (const float*)d_in[4];
    const float* b_out    = (const float*)d_in[5];
    const int*   edge_src = (const int*)d_in[6];
    const int*   out_verts = (const int*)d_in[n_in - 1];
    const int    v_out     = in_sizes[n_in - 1];

    float* out = (float*)d_out;
    (void)out_size;

    /* 1) input layer GEMM + relu */
    {
        dim3 grid(BATCH / BN, (PER_LAYER + BM - 1) / BM);
        gemm_in_kernel<<<grid, 256>>>(x, W_in, b_in);
    }

    /* 2) 7 sequential sparse layers (default stream serializes) */
    for (int l = 1; l < N_LAYERS; l++) {
        dim3 grid(BATCH / (128 * 4), PER_LAYER);
        spmm_layer_kernel<<<grid, 128>>>(w_edge, edge_src, l);
    }

    /* 3) output projection */
    {
        dim3 grid(BATCH / 256, NCHUNKS);
        out_partial_kernel<<<grid, 256>>>(W_out, out_verts, v_out);
        out_final_kernel<<<(BATCH * OUT_DIM + 255) / 256, 256>>>(b_out, out);
    }
}

// round 3
// speedup vs baseline: 1.0287x; 1.0287x over previous
#include <cuda_runtime.h>
#include <cuda_bf16.h>
#include <cstdint>
#include <math.h>

#define N_NODES   4000
#define N_LAYERS  8
#define PER_LAYER 500
#define IN_DEG    32
#define BATCH     2048
#define IN_DIM    784
#define OUT_DIM   10
#define EDGES_PER_LAYER (PER_LAYER * IN_DEG)   /* 16000 */
#define NCHUNKS_OUT 8

/* ---- GEMM config (mma.sync bf16, 3-term split) ---- */
#define KP    832                 /* K padded: 26 chunks of 32 */
#define KC    32
#define NKCH  (KP / KC)           /* 26 */
#define NPAD  512                 /* PER_LAYER padded */
#define RS    40                  /* smem row stride, elems (80 B, 16B-mult) */
#define ST    15360               /* elems per stage: 2*128*40 + 2*64*40 */
#define OFF_AH 0
#define OFF_AL (128 * RS)         /* 5120  */
#define OFF_BH (2 * 128 * RS)     /* 10240 */
#define OFF_BL (2 * 128 * RS + 64 * RS) /* 12800 */
#define GEMM_SMEM_BYTES (2 * ST * 2)    /* 61440 */

/* ---- device scratch (allocation-free) ---- */
__device__ __align__(16) float g_h[(size_t)N_NODES * BATCH];
__device__ __align__(16) float g_part[NCHUNKS_OUT * BATCH * OUT_DIM];
__device__ __align__(16) __nv_bfloat16 g_xhi[(size_t)BATCH * KP];
__device__ __align__(16) __nv_bfloat16 g_xlo[(size_t)BATCH * KP];
__device__ __align__(16) __nv_bfloat16 g_whi[(size_t)NPAD * KP];
__device__ __align__(16) __nv_bfloat16 g_wlo[(size_t)NPAD * KP];

/* ================= asm helpers (sm_80-era: legal on compute_100) ===== */
__device__ __forceinline__ uint32_t smem_u32(const void* p) {
    uint32_t a;
    asm("{ .reg .u64 t; cvta.to.shared.u64 t, %1; cvt.u32.u64 %0, t; }"
        : "=r"(a) : "l"(p));
    return a;
}

#define CP16(dst, src) \
    asm volatile("cp.async.cg.shared.global [%0], [%1], 16;" \
                 :: "r"(dst), "l"(src))
#define CP_COMMIT() asm volatile("cp.async.commit_group;" ::: "memory")
#define CP_WAIT1()  asm volatile("cp.async.wait_group 1;"  ::: "memory")

#define LDSM4(R, addr) \
    asm volatile("ldmatrix.sync.aligned.m8n8.x4.shared.b16 {%0,%1,%2,%3}, [%4];" \
                 : "=r"((R)[0]), "=r"((R)[1]), "=r"((R)[2]), "=r"((R)[3]) \
                 : "r"(addr))

#define MMA_BF16(acc, a, b0, b1) \
    asm volatile("mma.sync.aligned.m16n8k16.row.col.f32.bf16.bf16.f32 " \
                 "{%0,%1,%2,%3}, {%4,%5,%6,%7}, {%8,%9}, {%0,%1,%2,%3};" \
                 : "+f"((acc)[0]), "+f"((acc)[1]), "+f"((acc)[2]), "+f"((acc)[3]) \
                 : "r"((a)[0]), "r"((a)[1]), "r"((a)[2]), "r"((a)[3]), \
                   "r"(b0), "r"(b1))

/* ================= Kernel 0: fp32 -> bf16 hi/lo split ================= */
__global__ __launch_bounds__(256) void split_x_kernel(const float* __restrict__ x) {
    int idx = blockIdx.x * 256 + threadIdx.x;
    if (idx >= BATCH * KP) return;
    int r = idx / KP, k = idx % KP;
    float v = (k < IN_DIM) ? x[(size_t)r * IN_DIM + k] : 0.f;
    __nv_bfloat16 hi = __float2bfloat16(v);
    g_xhi[idx] = hi;
    g_xlo[idx] = __float2bfloat16(v - __bfloat162float(hi));
}

__global__ __launch_bounds__(256) void split_w_kernel(const float* __restrict__ W) {
    int idx = blockIdx.x * 256 + threadIdx.x;
    if (idx >= NPAD * KP) return;
    int r = idx / KP, k = idx % KP;
    float v = (r < PER_LAYER && k < IN_DIM) ? W[(size_t)r * IN_DIM + k] : 0.f;
    __nv_bfloat16 hi = __float2bfloat16(v);
    g_whi[idx] = hi;
    g_wlo[idx] = __float2bfloat16(v - __bfloat162float(hi));
}

/* ================= Kernel 1: input GEMM via mma.sync =================
   C[batch 2048, vert 512] = X[2048,832] * W^T[832,512], 3-term bf16.
   CTA 128x64, warp 64x32 (2x2 warps), K pipelined 32/chunk, cp.async x2. */
__global__ __launch_bounds__(128) void gemm_in_mma(const float* __restrict__ bias) {
    extern __shared__ __align__(16) __nv_bfloat16 sm[];
    const uint32_t smb = smem_u32(sm);

    const int tid  = threadIdx.x;
    const int lane = tid & 31, warp = tid >> 5;
    const int m0 = blockIdx.x * 128;     /* batch tile base */
    const int n0 = blockIdx.y * 64;      /* vertex tile base */
    const int wm = (warp & 1) * 64;      /* warp m offset in tile */
    const int wn = (warp >> 1) * 32;     /* warp n offset in tile */

    const int g   = lane >> 2;           /* 0..7  */
    const int tig = lane & 3;            /* 0..3  */
    const int quad = lane >> 3;          /* 0..3 ldmatrix quadrant */
    const int qr   = lane & 7;

    /* per-lane ldmatrix element offsets within a [16x16]/[16x16] tile */
    const int a_off = ((quad & 1) * 8 + qr) * RS + (quad >> 1) * 8;
    const int b_off = ((quad >> 1) * 8 + qr) * RS + (quad & 1) * 8;

    /* cp.async source bases for this thread (row ownership) */
    const __nv_bfloat16* srcAh = &g_xhi[(size_t)(m0 + tid) * KP];
    const __nv_bfloat16* srcAl = &g_xlo[(size_t)(m0 + tid) * KP];
    const __nv_bfloat16* srcB  = (tid < 64)
        ? &g_whi[(size_t)(n0 + tid) * KP]
        : &g_wlo[(size_t)(n0 + tid - 64) * KP];
    const int dstB_off = (tid < 64) ? (OFF_BH + tid * RS)
                                    : (OFF_BL + (tid - 64) * RS);

    float acc[4][4][4];
    #pragma unroll
    for (int i = 0; i < 4; i++)
        #pragma unroll
        for (int j = 0; j < 4; j++)
            #pragma unroll
            for (int q = 0; q < 4; q++) acc[i][j][q] = 0.f;

    /* issue one K-chunk's cp.async group into stage s */
    auto issue = [&](int c, int s) {
        const int k0 = c * KC;
        const uint32_t base = smb + (uint32_t)(s * ST) * 2;
        #pragma unroll
        for (int kk = 0; kk < 4; kk++) {
            CP16(base + (OFF_AH + tid * RS + kk * 8) * 2, srcAh + k0 + kk * 8);
            CP16(base + (OFF_AL + tid * RS + kk * 8) * 2, srcAl + k0 + kk * 8);
            CP16(base + (dstB_off + kk * 8) * 2,          srcB  + k0 + kk * 8);
        }
    };

    issue(0, 0); CP_COMMIT();
    issue(1, 1); CP_COMMIT();

    for (int c = 0; c < NKCH; c++) {
        const int s = c & 1;
        CP_WAIT1();
        __syncthreads();

        const uint32_t base = smb + (uint32_t)(s * ST) * 2;
        #pragma unroll
        for (int ks = 0; ks < KC; ks += 16) {
            uint32_t ah[4][4], al[4][4], bh[2][4], bl[2][4];
            #pragma unroll
            for (int mi = 0; mi < 4; mi++) {
                const uint32_t ao = base + (uint32_t)((wm + mi * 16) * RS + ks + a_off) * 2;
                LDSM4(ah[mi], ao + OFF_AH * 2);
                LDSM4(al[mi], ao + OFF_AL * 2);
            }
            #pragma unroll
            for (int njp = 0; njp < 2; njp++) {
                const uint32_t bo = base + (uint32_t)((wn + njp * 16) * RS + ks + b_off) * 2;
                LDSM4(bh[njp], bo + OFF_BH * 2);
                LDSM4(bl[njp], bo + OFF_BL * 2);
            }
            #pragma unroll
            for (int mi = 0; mi < 4; mi++) {
                #pragma unroll
                for (int njp = 0; njp < 2; njp++) {
                    #pragma unroll
                    for (int sub = 0; sub < 2; sub++) {
                        float* a4 = acc[mi][njp * 2 + sub];
                        MMA_BF16(a4, ah[mi], bh[njp][sub * 2], bh[njp][sub * 2 + 1]);
                        MMA_BF16(a4, al[mi], bh[njp][sub * 2], bh[njp][sub * 2 + 1]);
                        MMA_BF16(a4, ah[mi], bl[njp][sub * 2], bl[njp][sub * 2 + 1]);
                    }
                }
            }
        }
        __syncthreads();
        if (c + 2 < NKCH) issue(c + 2, s);
        CP_COMMIT();                      /* empty groups keep wait count valid */
    }

    /* epilogue: acc[mi][nj] -> C rows m/m+8, cols n/n+1; write g_h[n][m] */
    #pragma unroll
    for (int mi = 0; mi < 4; mi++) {
        const int m = m0 + wm + mi * 16 + g;
        #pragma unroll
        for (int nj = 0; nj < 4; nj++) {
            const int n = n0 + wn + nj * 8 + 2 * tig;
            if (n < PER_LAYER) {          /* n even; n+1 <= 499 whenever n < 500 */
                const float b0 = __ldg(&bias[n]);
                const float b1 = __ldg(&bias[n + 1]);
                float* a4 = acc[mi][nj];
                g_h[(size_t)n * BATCH + m]           = fmaxf(a4[0] + b0, 0.f);
                g_h[(size_t)(n + 1) * BATCH + m]     = fmaxf(a4[1] + b1, 0.f);
                g_h[(size_t)n * BATCH + m + 8]       = fmaxf(a4[2] + b0, 0.f);
                g_h[(size_t)(n + 1) * BATCH + m + 8] = fmaxf(a4[3] + b1, 0.f);
            }
        }
    }
}

/* ================= Kernel 2: one DAG layer (pipelined gather) ========= */
__global__ __launch_bounds__(128) void spmm_layer_kernel(
    const float* __restrict__ w_edge,
    const int*   __restrict__ edge_src,
    const int layer)
{
    const int v = blockIdx.y;
    const int c = (blockIdx.x * 128 + threadIdx.x) * 4;
    const int base = (layer - 1) * EDGES_PER_LAYER + v * IN_DEG;

    __shared__ int   s_src[IN_DEG];
    __shared__ float s_w[IN_DEG];
    if (threadIdx.x < IN_DEG) {
        s_src[threadIdx.x] = edge_src[base + threadIdx.x];
        s_w[threadIdx.x]   = w_edge[base + threadIdx.x];
    }
    __syncthreads();

    const float* __restrict__ hp = g_h;
    float ax = 0.f, ay = 0.f, az = 0.f, aw = 0.f;

    float4 cur[8];
    #pragma unroll
    for (int e = 0; e < 8; e++)
        cur[e] = *reinterpret_cast<const float4*>(&hp[(size_t)s_src[e] * BATCH + c]);

    #pragma unroll
    for (int gq = 1; gq < 4; gq++) {
        float4 nxt[8];
        #pragma unroll
        for (int e = 0; e < 8; e++)
            nxt[e] = *reinterpret_cast<const float4*>(&hp[(size_t)s_src[gq * 8 + e] * BATCH + c]);
        #pragma unroll
        for (int e = 0; e < 8; e++) {
            const float w = s_w[(gq - 1) * 8 + e];
            ax += w * cur[e].x; ay += w * cur[e].y;
            az += w * cur[e].z; aw += w * cur[e].w;
        }
        #pragma unroll
        for (int e = 0; e < 8; e++) cur[e] = nxt[e];
    }
    #pragma unroll
    for (int e = 0; e < 8; e++) {
        const float w = s_w[24 + e];
        ax += w * cur[e].x; ay += w * cur[e].y;
        az += w * cur[e].z; aw += w * cur[e].w;
    }

    const int dst = layer * PER_LAYER + v;
    float4 r;
    r.x = fmaxf(ax, 0.f); r.y = fmaxf(ay, 0.f);
    r.z = fmaxf(az, 0.f); r.w = fmaxf(aw, 0.f);
    *reinterpret_cast<float4*>(&g_h[(size_t)dst * BATCH + c]) = r;
}

/* ================= Kernel 3a/3b: output projection ================= */
__global__ __launch_bounds__(256) void out_partial_kernel(
    const float* __restrict__ W_out,
    const int*   __restrict__ out_verts,
    const int v_out)
{
    const int b = blockIdx.x * blockDim.x + threadIdx.x;
    const int chunk = blockIdx.y;
    const int csz = (v_out + NCHUNKS_OUT - 1) / NCHUNKS_OUT;
    const int v0 = chunk * csz;
    const int v1 = (v0 + csz < v_out) ? (v0 + csz) : v_out;

    float acc[OUT_DIM];
    #pragma unroll
    for (int o = 0; o < OUT_DIM; o++) acc[o] = 0.f;

    for (int v = v0; v < v1; v++) {
        const int vert = __ldg(&out_verts[v]);
        const float hv = g_h[(size_t)vert * BATCH + b];
        #pragma unroll
        for (int o = 0; o < OUT_DIM; o++)
            acc[o] += hv * __ldg(&W_out[(size_t)o * v_out + v]);
    }
    float* p = &g_part[((size_t)chunk * BATCH + b) * OUT_DIM];
    #pragma unroll
    for (int o = 0; o < OUT_DIM; o++) p[o] = acc[o];
}

__global__ __launch_bounds__(256) void out_final_kernel(
    const float* __restrict__ b_out,
    float* __restrict__ out)
{
    const int idx = blockIdx.x * blockDim.x + threadIdx.x;
    if (idx < BATCH * OUT_DIM) {
        const int o = idx % OUT_DIM;
        float s = b_out[o];
        #pragma unroll
        for (int ch = 0; ch < NCHUNKS_OUT; ch++)
            s += g_part[(size_t)ch * BATCH * OUT_DIM + idx];
        out[idx] = s;
    }
}

/* ================= launcher ================= */
extern "C" void kernel_launch(void* const* d_in, const int* in_sizes, int n_in,
                              void* d_out, int out_size)
{
    const float* x        = (const float*)d_in[0];
    const float* W_in     = (const float*)d_in[1];
    const float* b_in     = (const float*)d_in[2];
    const float* w_edge   = (const float*)d_in[3];
    const float* W_out    = (const float*)d_in[4];
    const float* b_out    = (const float*)d_in[5];
    const int*   edge_src = (const int*)d_in[6];
    const int*   out_verts = (const int*)d_in[n_in - 1];
    const int    v_out     = in_sizes[n_in - 1];
    float* out = (float*)d_out;
    (void)out_size;

    static bool attr_done = false;
    if (!attr_done) {
        cudaFuncSetAttribute(gemm_in_mma,
                             cudaFuncAttributeMaxDynamicSharedMemorySize,
                             GEMM_SMEM_BYTES);
        attr_done = true;
    }

    /* 0) fp32 -> bf16 hi/lo splits (padded to KP / NPAD) */
    split_x_kernel<<<(BATCH * KP + 255) / 256, 256>>>(x);
    split_w_kernel<<<(NPAD * KP + 255) / 256, 256>>>(W_in);

    /* 1) input GEMM on tensor cores (mma.sync) */
    gemm_in_mma<<<dim3(BATCH / 128, NPAD / 64), 128, GEMM_SMEM_BYTES>>>(b_in);

    /* 2) 7 sequential sparse layers */
    for (int l = 1; l < N_LAYERS; l++) {
        dim3 grid(BATCH / (128 * 4), PER_LAYER);
        spmm_layer_kernel<<<grid, 128>>>(w_edge, edge_src, l);
    }

    /* 3) output projection */
    {
        dim3 grid(BATCH / 256, NCHUNKS_OUT);
        out_partial_kernel<<<grid, 256>>>(W_out, out_verts, v_out);
        out_final_kernel<<<(BATCH * OUT_DIM + 255) / 256, 256>>>(b_out, out);
    }
}

// round 5
// speedup vs baseline: 1.1311x; 1.0996x over previous
#include <cuda_runtime.h>
#include <cuda_bf16.h>
#include <cstdint>
#include <math.h>

#define N_NODES   4000
#define N_LAYERS  8
#define PER_LAYER 500
#define IN_DEG    32
#define BATCH     2048
#define IN_DIM    784
#define OUT_DIM   10
#define EDGES_PER_LAYER (PER_LAYER * IN_DEG)
#define NCHUNKS_OUT 8

/* ---- GEMM config: CTA 64x64, 2x2 warps of 32x32, 3-term bf16 ---- */
#define KP    832                 /* K padded: 26 chunks of 32 */
#define KC    32
#define NKCH  (KP / KC)           /* 26 */
#define NPAD  512
#define RS    40                  /* smem row stride elems (80 B) */
#define OFF_AH 0
#define OFF_AL (64 * RS)
#define OFF_BH (128 * RS)
#define OFF_BL (192 * RS)
#define ST    (256 * RS)          /* elems per stage = 10240 (20480 B) */
#define GEMM_SMEM_BYTES (2 * ST * 2)    /* 40960 B (< 48K default) */

/* ---- device scratch ---- */
__device__ __align__(16) float g_h[(size_t)N_NODES * BATCH];
__device__ __align__(16) float g_part[NCHUNKS_OUT * BATCH * OUT_DIM];
__device__ __align__(16) __nv_bfloat16 g_xhi[(size_t)BATCH * KP];
__device__ __align__(16) __nv_bfloat16 g_xlo[(size_t)BATCH * KP];
__device__ __align__(16) __nv_bfloat16 g_whi[(size_t)NPAD * KP];
__device__ __align__(16) __nv_bfloat16 g_wlo[(size_t)NPAD * KP];

/* ================= asm helpers ================= */
__device__ __forceinline__ uint32_t smem_u32(const void* p) {
    uint32_t a;
    asm("{ .reg .u64 t; cvta.to.shared.u64 t, %1; cvt.u32.u64 %0, t; }"
        : "=r"(a) : "l"(p));
    return a;
}

#define CP16(dst, src) \
    asm volatile("cp.async.cg.shared.global [%0], [%1], 16;" \
                 :: "r"(dst), "l"(src))
#define CP_COMMIT() asm volatile("cp.async.commit_group;" ::: "memory")
#define CP_WAIT1()  asm volatile("cp.async.wait_group 1;"  ::: "memory")

#define LDSM4(R, addr) \
    asm volatile("ldmatrix.sync.aligned.m8n8.x4.shared.b16 {%0,%1,%2,%3}, [%4];" \
                 : "=r"((R)[0]), "=r"((R)[1]), "=r"((R)[2]), "=r"((R)[3]) \
                 : "r"(addr))

#define MMA_BF16(acc, a, b0, b1) \
    asm volatile("mma.sync.aligned.m16n8k16.row.col.f32.bf16.bf16.f32 " \
                 "{%0,%1,%2,%3}, {%4,%5,%6,%7}, {%8,%9}, {%0,%1,%2,%3};" \
                 : "+f"((acc)[0]), "+f"((acc)[1]), "+f"((acc)[2]), "+f"((acc)[3]) \
                 : "r"((a)[0]), "r"((a)[1]), "r"((a)[2]), "r"((a)[3]), \
                   "r"(b0), "r"(b1))

/* ======= Kernel 0: fused fp32 -> bf16 hi/lo split (x and W) ======= */
__global__ __launch_bounds__(256) void split_kernel(
    const float* __restrict__ x, const float* __restrict__ W)
{
    int idx = blockIdx.x * 256 + threadIdx.x;
    if (idx < BATCH * KP) {
        int r = idx / KP, k = idx % KP;
        float v = (k < IN_DIM) ? x[(size_t)r * IN_DIM + k] : 0.f;
        __nv_bfloat16 hi = __float2bfloat16(v);
        g_xhi[idx] = hi;
        g_xlo[idx] = __float2bfloat16(v - __bfloat162float(hi));
    } else {
        int j = idx - BATCH * KP;
        if (j >= NPAD * KP) return;
        int r = j / KP, k = j % KP;
        float v = (r < PER_LAYER && k < IN_DIM) ? W[(size_t)r * IN_DIM + k] : 0.f;
        __nv_bfloat16 hi = __float2bfloat16(v);
        g_whi[j] = hi;
        g_wlo[j] = __float2bfloat16(v - __bfloat162float(hi));
    }
}

/* ======= Kernel 1: input GEMM, CTA 64x64, grid 256 CTAs ======= */
__global__ __launch_bounds__(128) void gemm_in_mma(const float* __restrict__ bias) {
    extern __shared__ __align__(16) __nv_bfloat16 sm[];
    const uint32_t smb = smem_u32(sm);

    const int tid  = threadIdx.x;
    const int lane = tid & 31, warp = tid >> 5;
    const int m0 = blockIdx.x * 64;      /* batch tile base */
    const int n0 = blockIdx.y * 64;      /* vertex tile base */
    const int wm = (warp & 1) * 32;
    const int wn = (warp >> 1) * 32;

    const int g    = lane >> 2;
    const int tig  = lane & 3;
    const int quad = lane >> 3;
    const int qr   = lane & 7;
    const int a_off = ((quad & 1) * 8 + qr) * RS + (quad >> 1) * 8;
    const int b_off = ((quad >> 1) * 8 + qr) * RS + (quad & 1) * 8;

    float acc[2][4][4];
    #pragma unroll
    for (int i = 0; i < 2; i++)
        #pragma unroll
        for (int j = 0; j < 4; j++)
            #pragma unroll
            for (int q = 0; q < 4; q++) acc[i][j][q] = 0.f;

    /* cp.async: 1024 CP16 per stage / 128 threads = 8 each.
       idx = tid + i*128: chunk = idx&3, row = (idx>>2)&63, tile = idx>>8 */
    auto issue = [&](int c, int s) {
        const int k0 = c * KC;
        const uint32_t base = smb + (uint32_t)(s * ST) * 2;
        #pragma unroll
        for (int i = 0; i < 8; i++) {
            const int idx   = tid + i * 128;
            const int chunk = idx & 3;
            const int row   = (idx >> 2) & 63;
            const int tile  = idx >> 8;
            const __nv_bfloat16* src;
            switch (tile) {
                case 0:  src = &g_xhi[(size_t)(m0 + row) * KP]; break;
                case 1:  src = &g_xlo[(size_t)(m0 + row) * KP]; break;
                case 2:  src = &g_whi[(size_t)(n0 + row) * KP]; break;
                default: src = &g_wlo[(size_t)(n0 + row) * KP]; break;
            }
            CP16(base + (uint32_t)(tile * 64 * RS + row * RS + chunk * 8) * 2,
                 src + k0 + chunk * 8);
        }
    };

    issue(0, 0); CP_COMMIT();
    issue(1, 1); CP_COMMIT();

    for (int c = 0; c < NKCH; c++) {
        const int s = c & 1;
        CP_WAIT1();
        __syncthreads();

        const uint32_t base = smb + (uint32_t)(s * ST) * 2;
        #pragma unroll
        for (int ks = 0; ks < KC; ks += 16) {
            uint32_t ah[2][4], al[2][4], bh[2][4], bl[2][4];
            #pragma unroll
            for (int mi = 0; mi < 2; mi++) {
                const uint32_t ao = base + (uint32_t)((wm + mi * 16) * RS + ks + a_off) * 2;
                LDSM4(ah[mi], ao + OFF_AH * 2);
                LDSM4(al[mi], ao + OFF_AL * 2);
            }
            #pragma unroll
            for (int njp = 0; njp < 2; njp++) {
                const uint32_t bo = base + (uint32_t)((wn + njp * 16) * RS + ks + b_off) * 2;
                LDSM4(bh[njp], bo + OFF_BH * 2);
                LDSM4(bl[njp], bo + OFF_BL * 2);
            }
            #pragma unroll
            for (int mi = 0; mi < 2; mi++) {
                #pragma unroll
                for (int njp = 0; njp < 2; njp++) {
                    #pragma unroll
                    for (int sub = 0; sub < 2; sub++) {
                        float* a4 = acc[mi][njp * 2 + sub];
                        MMA_BF16(a4, ah[mi], bh[njp][sub * 2], bh[njp][sub * 2 + 1]);
                        MMA_BF16(a4, al[mi], bh[njp][sub * 2], bh[njp][sub * 2 + 1]);
                        MMA_BF16(a4, ah[mi], bl[njp][sub * 2], bl[njp][sub * 2 + 1]);
                    }
                }
            }
        }
        __syncthreads();
        if (c + 2 < NKCH) issue(c + 2, s);
        CP_COMMIT();
    }

    /* epilogue -> g_h[n][m], relu(acc + bias) */
    #pragma unroll
    for (int mi = 0; mi < 2; mi++) {
        const int m = m0 + wm + mi * 16 + g;
        #pragma unroll
        for (int nj = 0; nj < 4; nj++) {
            const int n = n0 + wn + nj * 8 + 2 * tig;
            if (n < PER_LAYER) {
                const float b0 = __ldg(&bias[n]);
                const float b1 = __ldg(&bias[n + 1]);
                float* a4 = acc[mi][nj];
                g_h[(size_t)n * BATCH + m]           = fmaxf(a4[0] + b0, 0.f);
                g_h[(size_t)(n + 1) * BATCH + m]     = fmaxf(a4[1] + b1, 0.f);
                g_h[(size_t)n * BATCH + m + 8]       = fmaxf(a4[2] + b0, 0.f);
                g_h[(size_t)(n + 1) * BATCH + m + 8] = fmaxf(a4[3] + b1, 0.f);
            }
        }
    }
}

/* ======= Kernel 2: DAG layer, rolling 8-deep gather pipeline ======= */
__global__ __launch_bounds__(128) void spmm_layer_kernel(
    const float* __restrict__ w_edge,
    const int*   __restrict__ edge_src,
    const int layer)
{
    const int v = blockIdx.y;
    const int c = (blockIdx.x * 128 + threadIdx.x) * 4;
    const int base = (layer - 1) * EDGES_PER_LAYER + v * IN_DEG;

    __shared__ int   s_src[IN_DEG];
    __shared__ float s_w[IN_DEG];
    if (threadIdx.x < IN_DEG) {
        s_src[threadIdx.x] = edge_src[base + threadIdx.x];
        s_w[threadIdx.x]   = w_edge[base + threadIdx.x];
    }
    __syncthreads();

    const float* __restrict__ hp = g_h;
    float ax = 0.f, ay = 0.f, az = 0.f, aw = 0.f;

    /* rolling window: always ~8 loads in flight, issue interleaved w/ fma */
    float4 buf[8];
    #pragma unroll
    for (int e = 0; e < 8; e++)
        buf[e] = *reinterpret_cast<const float4*>(&hp[(size_t)s_src[e] * BATCH + c]);

    #pragma unroll
    for (int e = 8; e < IN_DEG; e++) {
        const float w = s_w[e - 8];
        const float4 o = buf[e & 7];
        buf[e & 7] = *reinterpret_cast<const float4*>(&hp[(size_t)s_src[e] * BATCH + c]);
        ax += w * o.x; ay += w * o.y; az += w * o.z; aw += w * o.w;
    }
    #pragma unroll
    for (int e = 0; e < 8; e++) {
        const float w = s_w[24 + e];
        ax += w * buf[e].x; ay += w * buf[e].y;
        az += w * buf[e].z; aw += w * buf[e].w;
    }

    const int dst = layer * PER_LAYER + v;
    float4 r;
    r.x = fmaxf(ax, 0.f); r.y = fmaxf(ay, 0.f);
    r.z = fmaxf(az, 0.f); r.w = fmaxf(aw, 0.f);
    *reinterpret_cast<float4*>(&g_h[(size_t)dst * BATCH + c]) = r;
}

/* ======= Kernel 3a/3b: output projection ======= */
__global__ __launch_bounds__(256) void out_partial_kernel(
    const float* __restrict__ W_out,
    const int*   __restrict__ out_verts,
    const int v_out)
{
    const int b = blockIdx.x * blockDim.x + threadIdx.x;
    const int chunk = blockIdx.y;
    const int csz = (v_out + NCHUNKS_OUT - 1) / NCHUNKS_OUT;
    const int v0 = chunk * csz;
    const int v1 = (v0 + csz < v_out) ? (v0 + csz) : v_out;

    float acc[OUT_DIM];
    #pragma unroll
    for (int o = 0; o < OUT_DIM; o++) acc[o] = 0.f;

    for (int v = v0; v < v1; v++) {
        const int vert = __ldg(&out_verts[v]);
        const float hv = g_h[(size_t)vert * BATCH + b];
        #pragma unroll
        for (int o = 0; o < OUT_DIM; o++)
            acc[o] += hv * __ldg(&W_out[(size_t)o * v_out + v]);
    }
    float* p = &g_part[((size_t)chunk * BATCH + b) * OUT_DIM];
    #pragma unroll
    for (int o = 0; o < OUT_DIM; o++) p[o] = acc[o];
}

__global__ __launch_bounds__(256) void out_final_kernel(
    const float* __restrict__ b_out,
    float* __restrict__ out)
{
    const int idx = blockIdx.x * blockDim.x + threadIdx.x;
    if (idx < BATCH * OUT_DIM) {
        const int o = idx % OUT_DIM;
        float s = b_out[o];
        #pragma unroll
        for (int ch = 0; ch < NCHUNKS_OUT; ch++)
            s += g_part[(size_t)ch * BATCH * OUT_DIM + idx];
        out[idx] = s;
    }
}

/* ======= launcher ======= */
extern "C" void kernel_launch(void* const* d_in, const int* in_sizes, int n_in,
                              void* d_out, int out_size)
{
    const float* x        = (const float*)d_in[0];
    const float* W_in     = (const float*)d_in[1];
    const float* b_in     = (const float*)d_in[2];
    const float* w_edge   = (const float*)d_in[3];
    const float* W_out    = (const float*)d_in[4];
    const float* b_out    = (const float*)d_in[5];
    const int*   edge_src = (const int*)d_in[6];
    const int*   out_verts = (const int*)d_in[n_in - 1];
    const int    v_out     = in_sizes[n_in - 1];
    float* out = (float*)d_out;
    (void)out_size;

    /* 0) fused split (one launch) */
    {
        const int tot = BATCH * KP + NPAD * KP;
        split_kernel<<<(tot + 255) / 256, 256>>>(x, W_in);
    }

    /* 1) input GEMM: 256 CTAs x 4 warps */
    gemm_in_mma<<<dim3(BATCH / 64, NPAD / 64), 128, GEMM_SMEM_BYTES>>>(b_in);

    /* 2) 7 sequential sparse layers */
    for (int l = 1; l < N_LAYERS; l++) {
        dim3 grid(BATCH / (128 * 4), PER_LAYER);
        spmm_layer_kernel<<<grid, 128>>>(w_edge, edge_src, l);
    }

    /* 3) output projection */
    {
        dim3 grid(BATCH / 256, NCHUNKS_OUT);
        out_partial_kernel<<<grid, 256>>>(W_out, out_verts, v_out);
        out_final_kernel<<<(BATCH * OUT_DIM + 255) / 256, 256>>>(b_out, out);
    }
}